// round 1
// baseline (speedup 1.0000x reference)
#include <cuda_runtime.h>

// Guided_Conv: 4096 independent 24x24x9 patches.
// patch n = b*256 + i*16 + j  (b=batch, i=patch-row, j=patch-col)
//   input  pixel (pr,pc,f): guidance/depth[ ((b*384 + i*24+pr)*384 + j*24+pc)*9 + f ]
//   output pixel (pr,pc,f): out[ n*5184 + (pr*24+pc)*9 + f ]   (contiguous block per patch)

#define NPIX   576            // 24*24
#define THREADS 576
#define ROW_F4 54             // 24*9/4 float4 per patch row
#define ROWSTRIDE4 864        // 384*9/4 float4 per image row

__global__ __launch_bounds__(THREADS, 2)
void guided_conv_kernel(const float* __restrict__ guidance,
                        const float* __restrict__ depth,
                        const float* __restrict__ conv_w,   // (3,3,9,9)
                        const float* __restrict__ conv_b,   // (9,)
                        const float* __restrict__ dense_w,  // (9,81)
                        const float* __restrict__ dense_b,  // (81,)
                        float* __restrict__ out)
{
    __shared__ __align__(16) float g_s[NPIX * 9];   // guidance patch [pix][f]
    __shared__ __align__(16) float d_s[NPIX * 9];   // depth patch    [pix][f]
    __shared__ float cw_s[729];                     // conv_w
    __shared__ float dw_s[729];                     // dense_w
    __shared__ float cb_s[9];
    __shared__ float db_s[81];
    __shared__ float c_s[81];                       // conv out [k=ky*3+kx][o]
    __shared__ float gap_s[9];
    __shared__ float dvec_s[81];                    // dense out [i][o]
    __shared__ float w1_s[81];                      // normalized depthwise kernel [k][f]
    __shared__ float w2_s[81];                      // normalized mix [i][o]

    const int n   = blockIdx.x;
    const int b   = n >> 8;
    const int pi  = (n >> 4) & 15;
    const int pj  = n & 15;
    const int tid = threadIdx.x;

    // ---- Phase 1: stage patches (float4) + weights into SMEM ----
    const int base4 = (((b * 384 + pi * 24) * 384 + pj * 24) * 9) >> 2;
    const float4* g4 = reinterpret_cast<const float4*>(guidance);
    const float4* d4 = reinterpret_cast<const float4*>(depth);
    float4* gs4 = reinterpret_cast<float4*>(g_s);
    float4* ds4 = reinterpret_cast<float4*>(d_s);

    for (int idx = tid; idx < 24 * ROW_F4; idx += THREADS) {
        const int pr = idx / ROW_F4;
        const int c4 = idx - pr * ROW_F4;
        const int gi = base4 + pr * ROWSTRIDE4 + c4;
        gs4[idx] = g4[gi];
        ds4[idx] = d4[gi];
    }
    for (int idx = tid; idx < 729; idx += THREADS) {
        cw_s[idx] = conv_w[idx];
        dw_s[idx] = dense_w[idx];
    }
    if (tid < 81) db_s[tid] = dense_b[tid];
    if (tid >= 96 && tid < 105) cb_s[tid - 96] = conv_b[tid - 96];
    __syncthreads();

    // ---- Phase 2: strided conv (tid<81)  ||  patch mean (warps 3..11) ----
    if (tid < 81) {
        const int o  = tid % 9;
        const int k  = tid / 9;
        const int ky = k / 3, kx = k % 3;
        float acc = cb_s[o];
        #pragma unroll
        for (int r = 0; r < 3; r++) {
            #pragma unroll
            for (int s = 0; s < 3; s++) {
                const float* gp = &g_s[((8 * ky + r) * 24 + 8 * kx + s) * 9];
                const float* wp = &cw_s[((r * 3 + s) * 9) * 9 + o];
                #pragma unroll
                for (int ii = 0; ii < 9; ii++)
                    acc += gp[ii] * wp[ii * 9];
            }
        }
        c_s[k * 9 + o] = acc;
    } else if (tid >= 96 && tid < 384) {
        const int f    = (tid - 96) >> 5;
        const int lane = tid & 31;
        float s = 0.f;
        #pragma unroll
        for (int p = 0; p < 18; p++)             // 576/32 pixels each
            s += g_s[(lane + 32 * p) * 9 + f];   // lane stride 9 -> conflict-free
        #pragma unroll
        for (int off = 16; off > 0; off >>= 1)
            s += __shfl_down_sync(0xffffffffu, s, off);
        if (lane == 0) gap_s[f] = s * (1.0f / 576.0f);
    }
    __syncthreads();

    // ---- Phase 3: dense (tid<81)  ||  W1 clip-by-norm (tid 96..104) ----
    if (tid < 81) {
        float acc = db_s[tid];
        #pragma unroll
        for (int ii = 0; ii < 9; ii++)
            acc += gap_s[ii] * dw_s[ii * 81 + tid];
        dvec_s[tid] = acc;
    } else if (tid >= 96 && tid < 105) {
        const int o = tid - 96;
        float ss = 0.f;
        #pragma unroll
        for (int k = 0; k < 9; k++) { const float v = c_s[k * 9 + o]; ss += v * v; }
        const float scale = 1.0f / fmaxf(sqrtf(ss), 1.0f);
        #pragma unroll
        for (int k = 0; k < 9; k++) w1_s[k * 9 + o] = c_s[k * 9 + o] * scale;
    }
    __syncthreads();

    // ---- Phase 4: W2 clip-by-norm (per output column, over input dim) ----
    if (tid < 9) {
        const int o = tid;
        float ss = 0.f;
        #pragma unroll
        for (int ii = 0; ii < 9; ii++) { const float v = dvec_s[ii * 9 + o]; ss += v * v; }
        const float scale = 1.0f / fmaxf(sqrtf(ss), 1.0f);
        #pragma unroll
        for (int ii = 0; ii < 9; ii++) w2_s[ii * 9 + o] = dvec_s[ii * 9 + o] * scale;
    }
    __syncthreads();

    // ---- Phase 5: fused depthwise 3x3 SAME conv + 9x9 channel mix ----
    const int p = tid / 24;
    const int q = tid - p * 24;

    float dc[9];
    #pragma unroll
    for (int ii = 0; ii < 9; ii++) dc[ii] = 0.f;

    #pragma unroll
    for (int dy = 0; dy < 3; dy++) {
        const int pp = p + dy - 1;
        if (pp < 0 || pp >= 24) continue;
        #pragma unroll
        for (int dx = 0; dx < 3; dx++) {
            const int qq = q + dx - 1;
            if (qq < 0 || qq >= 24) continue;
            const float* dp = &d_s[(pp * 24 + qq) * 9];   // lane stride 9 -> conflict-free
            const float* wp = &w1_s[(dy * 3 + dx) * 9];   // broadcast
            #pragma unroll
            for (int ii = 0; ii < 9; ii++)
                dc[ii] += dp[ii] * wp[ii];
        }
    }

    float* op = out + (size_t)n * 5184 + tid * 9;
    #pragma unroll
    for (int o = 0; o < 9; o++) {
        float acc = 0.f;
        #pragma unroll
        for (int ii = 0; ii < 9; ii++)
            acc += dc[ii] * w2_s[ii * 9 + o];             // broadcast
        op[o] = acc;
    }
}

extern "C" void kernel_launch(void* const* d_in, const int* in_sizes, int n_in,
                              void* d_out, int out_size) {
    const float* guidance = (const float*)d_in[0];
    const float* depth    = (const float*)d_in[1];
    const float* conv_w   = (const float*)d_in[2];
    const float* conv_b   = (const float*)d_in[3];
    const float* dense_w  = (const float*)d_in[4];
    const float* dense_b  = (const float*)d_in[5];
    float* out = (float*)d_out;

    guided_conv_kernel<<<4096, THREADS>>>(guidance, depth, conv_w, conv_b,
                                          dense_w, dense_b, out);
}

// round 2
// speedup vs baseline: 1.2345x; 1.2345x over previous
#include <cuda_runtime.h>

// Guided_Conv: 4096 independent 24x24x9 patches.
// patch n = b*256 + i*16 + j  (b=batch, i=patch-row, j=patch-col)
//   input  pixel (pr,pc,f): guidance/depth[ ((b*384 + i*24+pr)*384 + j*24+pc)*9 + f ]
//   output pixel (pr,pc,f): out[ n*5184 + (pr*24+pc)*9 + f ]   (contiguous block per patch)

#define NPIX   576            // 24*24
#define THREADS 576
#define ROW_F4 54             // 24*9/4 float4 per patch row
#define ROWSTRIDE4 864        // 384*9/4 float4 per image row

__global__ __launch_bounds__(THREADS, 3)
void guided_conv_kernel(const float* __restrict__ guidance,
                        const float* __restrict__ depth,
                        const float* __restrict__ conv_w,   // (3,3,9,9)
                        const float* __restrict__ conv_b,   // (9,)
                        const float* __restrict__ dense_w,  // (9,81)
                        const float* __restrict__ dense_b,  // (81,)
                        float* __restrict__ out)
{
    __shared__ __align__(16) float g_s[NPIX * 9];   // guidance patch, then OUTPUT staging
    __shared__ __align__(16) float d_s[NPIX * 9];   // depth patch    [pix][f]
    __shared__ float cw_s[729];                     // conv_w
    __shared__ float dw_s[729];                     // dense_w
    __shared__ float cb_s[9];
    __shared__ float db_s[81];
    __shared__ float c_s[81];                       // conv out [k=ky*3+kx][o]
    __shared__ float gap_s[9];
    __shared__ float dvec_s[81];                    // dense out [i][o]
    __shared__ float w1_s[81];                      // normalized depthwise kernel [k][f]
    __shared__ float w2_s[81];                      // normalized mix [i][o]

    const int n   = blockIdx.x;
    const int b   = n >> 8;
    const int pi  = (n >> 4) & 15;
    const int pj  = n & 15;
    const int tid = threadIdx.x;

    // ---- Phase 1: stage patches (float4) + weights into SMEM ----
    const int base4 = (((b * 384 + pi * 24) * 384 + pj * 24) * 9) >> 2;
    const float4* g4 = reinterpret_cast<const float4*>(guidance);
    const float4* d4 = reinterpret_cast<const float4*>(depth);
    float4* gs4 = reinterpret_cast<float4*>(g_s);
    float4* ds4 = reinterpret_cast<float4*>(d_s);

    for (int idx = tid; idx < 24 * ROW_F4; idx += THREADS) {
        const int pr = idx / ROW_F4;
        const int c4 = idx - pr * ROW_F4;
        const int gi = base4 + pr * ROWSTRIDE4 + c4;
        gs4[idx] = g4[gi];
        ds4[idx] = d4[gi];
    }
    for (int idx = tid; idx < 729; idx += THREADS) {
        cw_s[idx] = conv_w[idx];
        dw_s[idx] = dense_w[idx];
    }
    if (tid < 81) db_s[tid] = dense_b[tid];
    if (tid >= 96 && tid < 105) cb_s[tid - 96] = conv_b[tid - 96];
    __syncthreads();

    // ---- Phase 2: strided conv (tid<81)  ||  patch mean (warps 3..11) ----
    if (tid < 81) {
        const int o  = tid % 9;
        const int k  = tid / 9;
        const int ky = k / 3, kx = k % 3;
        float acc = cb_s[o];
        #pragma unroll
        for (int r = 0; r < 3; r++) {
            #pragma unroll
            for (int s = 0; s < 3; s++) {
                const float* gp = &g_s[((8 * ky + r) * 24 + 8 * kx + s) * 9];
                const float* wp = &cw_s[((r * 3 + s) * 9) * 9 + o];
                #pragma unroll
                for (int ii = 0; ii < 9; ii++)
                    acc += gp[ii] * wp[ii * 9];
            }
        }
        c_s[k * 9 + o] = acc;
    } else if (tid >= 96 && tid < 384) {
        const int f    = (tid - 96) >> 5;
        const int lane = tid & 31;
        float s = 0.f;
        #pragma unroll
        for (int p = 0; p < 18; p++)             // 576/32 pixels each
            s += g_s[(lane + 32 * p) * 9 + f];   // lane stride 9 -> conflict-free
        #pragma unroll
        for (int off = 16; off > 0; off >>= 1)
            s += __shfl_down_sync(0xffffffffu, s, off);
        if (lane == 0) gap_s[f] = s * (1.0f / 576.0f);
    }
    __syncthreads();

    // ---- Phase 3: dense (tid<81)  ||  W1 clip-by-norm (tid 96..104) ----
    if (tid < 81) {
        float acc = db_s[tid];
        #pragma unroll
        for (int ii = 0; ii < 9; ii++)
            acc += gap_s[ii] * dw_s[ii * 81 + tid];
        dvec_s[tid] = acc;
    } else if (tid >= 96 && tid < 105) {
        const int o = tid - 96;
        float ss = 0.f;
        #pragma unroll
        for (int k = 0; k < 9; k++) { const float v = c_s[k * 9 + o]; ss += v * v; }
        const float scale = 1.0f / fmaxf(sqrtf(ss), 1.0f);
        #pragma unroll
        for (int k = 0; k < 9; k++) w1_s[k * 9 + o] = c_s[k * 9 + o] * scale;
    }
    __syncthreads();

    // ---- Phase 4: W2 clip-by-norm (per output column, over input dim) ----
    if (tid < 9) {
        const int o = tid;
        float ss = 0.f;
        #pragma unroll
        for (int ii = 0; ii < 9; ii++) { const float v = dvec_s[ii * 9 + o]; ss += v * v; }
        const float scale = 1.0f / fmaxf(sqrtf(ss), 1.0f);
        #pragma unroll
        for (int ii = 0; ii < 9; ii++) w2_s[ii * 9 + o] = dvec_s[ii * 9 + o] * scale;
    }
    __syncthreads();

    // ---- Phase 5: fused depthwise 3x3 SAME conv + 9x9 channel mix ----
    const int p = tid / 24;
    const int q = tid - p * 24;

    float dc[9];
    #pragma unroll
    for (int ii = 0; ii < 9; ii++) dc[ii] = 0.f;

    #pragma unroll
    for (int dy = 0; dy < 3; dy++) {
        const int pp = p + dy - 1;
        if (pp < 0 || pp >= 24) continue;
        #pragma unroll
        for (int dx = 0; dx < 3; dx++) {
            const int qq = q + dx - 1;
            if (qq < 0 || qq >= 24) continue;
            const float* dp = &d_s[(pp * 24 + qq) * 9];   // lane stride 9 -> conflict-free
            const float* wp = &w1_s[(dy * 3 + dx) * 9];   // broadcast
            #pragma unroll
            for (int ii = 0; ii < 9; ii++)
                dc[ii] += dp[ii] * wp[ii];
        }
    }

    // Mix channels and stage result in SMEM (g_s is dead after phase 3;
    // its 5184 floats are exactly one output patch in [pix][f] layout).
    #pragma unroll
    for (int o = 0; o < 9; o++) {
        float acc = 0.f;
        #pragma unroll
        for (int ii = 0; ii < 9; ii++)
            acc += dc[ii] * w2_s[ii * 9 + o];             // broadcast
        g_s[tid * 9 + o] = acc;                           // stride 9 -> conflict-free
    }
    __syncthreads();

    // ---- Phase 6: coalesced float4 store of the whole patch ----
    const float4* src = reinterpret_cast<const float4*>(g_s);
    float4* dst = reinterpret_cast<float4*>(out + (size_t)n * 5184);
    #pragma unroll 3
    for (int idx = tid; idx < 1296; idx += THREADS)
        dst[idx] = src[idx];
}

extern "C" void kernel_launch(void* const* d_in, const int* in_sizes, int n_in,
                              void* d_out, int out_size) {
    const float* guidance = (const float*)d_in[0];
    const float* depth    = (const float*)d_in[1];
    const float* conv_w   = (const float*)d_in[2];
    const float* conv_b   = (const float*)d_in[3];
    const float* dense_w  = (const float*)d_in[4];
    const float* dense_b  = (const float*)d_in[5];
    float* out = (float*)d_out;

    guided_conv_kernel<<<4096, THREADS>>>(guidance, depth, conv_w, conv_b,
                                          dense_w, dense_b, out);
}